// round 2
// baseline (speedup 1.0000x reference)
#include <cuda_runtime.h>
#include <cuda_bf16.h>
#include <mma.h>

using namespace nvcuda;

// Problem dims (fixed by the reference)
#define T_   16
#define B_   8192
#define DIN  512
#define DH   1024
#define DOUT 256

// Scratch: hidden activations laid out [b][t][h] so layer-3 becomes a single
// GEMM with K = T_*DH contiguous per row, matching W3 flattened [T_*DH, DOUT].
__device__ float g_h1[(size_t)B_ * T_ * DH];  // 512 MB
__device__ float g_h2[(size_t)B_ * T_ * DH];  // 512 MB

// ---------------------------------------------------------------------------
// Generic tf32 WMMA GEMM: C = op(A @ B + bias), batched over blockIdx.z trees.
//   A: row-major, row stride lda, per-tree element offset a_t_off
//   B: row-major [K, N] contiguous, per-tree element offset b_t_off
//   bias: bias_rows rows of length N (summed), per-tree offset bias_t_off
//   C: row stride ldc, per-tree offset c_t_off
//   out = (acc + sum_bias) * scale, optional ReLU
// All of M (8192), N (1024/256), K (512/1024/16384) divide the tile sizes,
// so no bounds checks anywhere.
// ---------------------------------------------------------------------------
constexpr int BM = 128, BN = 128, BK = 32;
constexpr int PAD_A = 4;  // sA leading dim 36 (multiple of 4 floats = 16B)

__global__ void __launch_bounds__(256, 2)
gemm_tf32_kernel(const float* __restrict__ A, const float* __restrict__ Bm,
                 const float* __restrict__ bias, float* __restrict__ C,
                 int K, int N,
                 long lda, long ldc,
                 long a_t_off, long b_t_off, long c_t_off, long bias_t_off,
                 int bias_rows, float scale, int relu)
{
    __shared__ float sA[BM][BK + PAD_A];   // 18 KB
    __shared__ float sB[BK][BN];           // 16 KB
    __shared__ float sC[8][16][20];        // 10 KB epilogue staging (per warp)

    const int t = blockIdx.z;
    const float* At = A    + (long)t * a_t_off;
    const float* Bt = Bm   + (long)t * b_t_off;
    const float* bt = bias + (long)t * bias_t_off;
    float*       Ct = C    + (long)t * c_t_off;

    const int tid  = threadIdx.x;
    const int w    = tid >> 5;
    const int lane = tid & 31;
    const int wm   = w & 3;   // warp row 0..3  (32 rows each)
    const int wn   = w >> 2;  // warp col 0..1  (64 cols each)
    const int m0   = blockIdx.x * BM;
    const int n0   = blockIdx.y * BN;

    wmma::fragment<wmma::accumulator, 16, 16, 8, float> acc[2][4];
    #pragma unroll
    for (int i = 0; i < 2; i++)
        #pragma unroll
        for (int j = 0; j < 4; j++)
            wmma::fill_fragment(acc[i][j], 0.0f);

    for (int k0 = 0; k0 < K; k0 += BK) {
        // ---- load A tile (BM x BK) as float4, convert to tf32 ----
        #pragma unroll
        for (int it = 0; it < 4; it++) {
            int s   = tid + it * 256;       // 1024 float4 slots
            int row = s >> 3;               // BK/4 = 8 float4 per row
            int c4  = (s & 7) << 2;
            float4 v = *reinterpret_cast<const float4*>(
                At + (long)(m0 + row) * lda + k0 + c4);
            sA[row][c4 + 0] = wmma::__float_to_tf32(v.x);
            sA[row][c4 + 1] = wmma::__float_to_tf32(v.y);
            sA[row][c4 + 2] = wmma::__float_to_tf32(v.z);
            sA[row][c4 + 3] = wmma::__float_to_tf32(v.w);
        }
        // ---- load B tile (BK x BN) ----
        #pragma unroll
        for (int it = 0; it < 4; it++) {
            int s   = tid + it * 256;
            int row = s >> 5;               // BN/4 = 32 float4 per row
            int c4  = (s & 31) << 2;
            float4 v = *reinterpret_cast<const float4*>(
                Bt + (long)(k0 + row) * N + n0 + c4);
            sB[row][c4 + 0] = wmma::__float_to_tf32(v.x);
            sB[row][c4 + 1] = wmma::__float_to_tf32(v.y);
            sB[row][c4 + 2] = wmma::__float_to_tf32(v.z);
            sB[row][c4 + 3] = wmma::__float_to_tf32(v.w);
        }
        __syncthreads();

        #pragma unroll
        for (int kk = 0; kk < BK; kk += 8) {
            wmma::fragment<wmma::matrix_a, 16, 16, 8, wmma::precision::tf32,
                           wmma::row_major> af[2];
            wmma::fragment<wmma::matrix_b, 16, 16, 8, wmma::precision::tf32,
                           wmma::row_major> bf[4];
            #pragma unroll
            for (int i = 0; i < 2; i++)
                wmma::load_matrix_sync(af[i], &sA[wm * 32 + i * 16][kk], BK + PAD_A);
            #pragma unroll
            for (int j = 0; j < 4; j++)
                wmma::load_matrix_sync(bf[j], &sB[kk][wn * 64 + j * 16], BN);
            #pragma unroll
            for (int i = 0; i < 2; i++)
                #pragma unroll
                for (int j = 0; j < 4; j++)
                    wmma::mma_sync(acc[i][j], af[i], bf[j], acc[i][j]);
        }
        __syncthreads();
    }

    // ---- epilogue: stage each 16x16 fragment through smem, fuse bias/ReLU ----
    #pragma unroll
    for (int i = 0; i < 2; i++) {
        #pragma unroll
        for (int j = 0; j < 4; j++) {
            wmma::store_matrix_sync(&sC[w][0][0], acc[i][j], 20, wmma::mem_row_major);
            __syncwarp();
            #pragma unroll
            for (int e = 0; e < 8; e++) {
                int idx = lane + e * 32;        // 256 elems / 32 lanes
                int r  = idx >> 4;
                int cc = idx & 15;
                int gm = m0 + wm * 32 + i * 16 + r;
                int gn = n0 + wn * 64 + j * 16 + cc;
                float bsum = 0.0f;
                for (int br = 0; br < bias_rows; br++)
                    bsum += bt[(long)br * N + gn];
                float v = (sC[w][r][cc] + bsum) * scale;
                if (relu) v = fmaxf(v, 0.0f);
                Ct[(long)gm * ldc + gn] = v;
            }
            __syncwarp();
        }
    }
}

// ---------------------------------------------------------------------------
// Launch: 3 grouped GEMMs.
//   L1: h1[b][t][:] = relu(x[b]    @ W1[t] + b1[t])   M=8192 K=512   N=1024, T=16
//   L2: h2[b][t][:] = relu(h1[b][t]@ W2[t] + b2[t])   M=8192 K=1024  N=1024, T=16
//   L3: out[b][:]   = (h2[b] @ W3flat + sum_t b3) /16 M=8192 K=16384 N=256,  T=1
// ---------------------------------------------------------------------------
extern "C" void kernel_launch(void* const* d_in, const int* in_sizes, int n_in,
                              void* d_out, int out_size)
{
    const float* x  = (const float*)d_in[0];  // [8192, 512]
    const float* W1 = (const float*)d_in[1];  // [16, 512, 1024]
    const float* b1 = (const float*)d_in[2];  // [16, 1024]
    const float* W2 = (const float*)d_in[3];  // [16, 1024, 1024]
    const float* b2 = (const float*)d_in[4];  // [16, 1024]
    const float* W3 = (const float*)d_in[5];  // [16, 1024, 256]
    const float* b3 = (const float*)d_in[6];  // [16, 256]
    float* out = (float*)d_out;               // [8192, 256]

    float* h1 = nullptr;
    float* h2 = nullptr;
    cudaGetSymbolAddress((void**)&h1, g_h1);
    cudaGetSymbolAddress((void**)&h2, g_h2);

    dim3 block(256);

    // Layer 1
    {
        dim3 grid(B_ / BM, DH / BN, T_);
        gemm_tf32_kernel<<<grid, block>>>(
            x, W1, b1, h1,
            /*K=*/DIN, /*N=*/DH,
            /*lda=*/DIN, /*ldc=*/(long)T_ * DH,
            /*a_t_off=*/0, /*b_t_off=*/(long)DIN * DH,
            /*c_t_off=*/DH, /*bias_t_off=*/DH,
            /*bias_rows=*/1, /*scale=*/1.0f, /*relu=*/1);
    }
    // Layer 2
    {
        dim3 grid(B_ / BM, DH / BN, T_);
        gemm_tf32_kernel<<<grid, block>>>(
            h1, W2, b2, h2,
            /*K=*/DH, /*N=*/DH,
            /*lda=*/(long)T_ * DH, /*ldc=*/(long)T_ * DH,
            /*a_t_off=*/DH, /*b_t_off=*/(long)DH * DH,
            /*c_t_off=*/DH, /*bias_t_off=*/DH,
            /*bias_rows=*/1, /*scale=*/1.0f, /*relu=*/1);
    }
    // Layer 3: single GEMM over K = T_*DH (tree-mean folded into scale),
    // bias = sum_t b3[t] applied with the same 1/16 scale.
    {
        dim3 grid(B_ / BM, DOUT / BN, 1);
        gemm_tf32_kernel<<<grid, block>>>(
            h2, W3, b3, out,
            /*K=*/T_ * DH, /*N=*/DOUT,
            /*lda=*/(long)T_ * DH, /*ldc=*/DOUT,
            /*a_t_off=*/0, /*b_t_off=*/0,
            /*c_t_off=*/0, /*bias_t_off=*/0,
            /*bias_rows=*/T_, /*scale=*/1.0f / T_, /*relu=*/0);
    }
}

// round 4
// speedup vs baseline: 3.8027x; 3.8027x over previous
#include <cuda_runtime.h>
#include <cstdint>

#define T_   16
#define B_   8192
#define DIN  512
#define DH   1024
#define DOUT 256
#define SPLITK 8
#define KSEG (T_*DH/SPLITK)   // 2048

// ---------------- scratch (allocation-free: __device__ globals) -------------
__device__ float g_x  [(size_t)B_*DIN];          // tf32-rounded x
__device__ float g_w1t[(size_t)T_*DH*DIN];       // W1^T [t][n][k]
__device__ float g_w2t[(size_t)T_*DH*DH];        // W2^T [t][n][k]
__device__ float g_w3t[(size_t)DOUT*T_*DH];      // W3^T [n][t*DH+k]
__device__ float g_h1 [(size_t)B_*T_*DH];        // h1 [b][t][h]
__device__ float g_h2 [(size_t)B_*T_*DH];        // h2 [b][t][h]
__device__ float g_part[(size_t)SPLITK*B_*DOUT]; // split-K partials

// ---------------- helpers ----------------------------------------------
__device__ __forceinline__ uint32_t smem_to_u32(const void* p) {
    uint32_t a;
    asm("{ .reg .u64 t; cvta.to.shared.u64 t, %1; cvt.u32.u64 %0, t; }"
        : "=r"(a) : "l"(p));
    return a;
}
__device__ __forceinline__ float to_tf32(float f) {
    float r; asm("cvt.rna.tf32.f32 %0, %1;" : "=f"(r) : "f"(f)); return r;
}
__device__ __forceinline__ void cp16(uint32_t s, const void* g) {
    asm volatile("cp.async.cg.shared.global [%0], [%1], 16;" :: "r"(s), "l"(g));
}
__device__ __forceinline__ void ldsm4(uint32_t* r, uint32_t addr) {
    asm volatile("ldmatrix.sync.aligned.m8n8.x4.shared.b16 {%0,%1,%2,%3}, [%4];"
        : "=r"(r[0]), "=r"(r[1]), "=r"(r[2]), "=r"(r[3]) : "r"(addr));
}
__device__ __forceinline__ void mma8(float* d, const uint32_t* a,
                                     uint32_t b0, uint32_t b1) {
    asm volatile(
        "mma.sync.aligned.m16n8k8.row.col.f32.tf32.tf32.f32 "
        "{%0,%1,%2,%3}, {%4,%5,%6,%7}, {%8,%9}, {%0,%1,%2,%3};"
        : "+f"(d[0]), "+f"(d[1]), "+f"(d[2]), "+f"(d[3])
        : "r"(a[0]), "r"(a[1]), "r"(a[2]), "r"(a[3]), "r"(b0), "r"(b1));
}

// ---------------- GEMM kernel ----------------------------------------------
// BM=128, BN=256, BK=32 floats. 256 threads = 8 warps as 2(M) x 4(N),
// warp tile 64x64 (mtiles=4 of m16, ntiles=8 of n8), m16n8k8 tf32 mma.
// 4-stage cp.async ring. Smem chunk swizzle: 16B chunk c -> c ^ (row & 7).
constexpr int STAGES      = 4;
constexpr int STAGE_BYTES = (128 + 256) * 32 * 4;         // 49152
constexpr int GEMM_SMEM   = STAGES * STAGE_BYTES;          // 196608

// flags: bit0 = add bias, bit1 = relu + tf32-round output
__global__ void __launch_bounds__(256, 1)
gemm_tc(const float* __restrict__ A, const float* __restrict__ B,
        const float* __restrict__ bias, float* __restrict__ C,
        int nk, long lda, long ldb, long ldc,
        long a_z, long b_z, long c_z, long bias_z, int flags)
{
    extern __shared__ char smem[];
    const uint32_t sb = smem_to_u32(smem);
    const int tid  = threadIdx.x;
    const int lane = tid & 31;
    const int wid  = tid >> 5;
    const int wm   = wid & 1;        // 2 M warp-rows (64 each)
    const int wn   = wid >> 1;       // 4 N warp-cols (64 each)
    const int z    = blockIdx.z;
    const long m0  = (long)blockIdx.x * 128;
    const long n0  = (long)blockIdx.y * 256;

    const float* Ag = A + (long)z * a_z + m0 * lda;
    const float* Bg = B + (long)z * b_z + n0 * ldb;

    // ---- cp.async source pointers / swizzled dest offsets ----
    const float* asrc[4]; uint32_t adst[4];
    #pragma unroll
    for (int i = 0; i < 4; i++) {
        int idx = tid + i * 256;          // 1024 chunks: row 0..127, c 0..7
        int r = idx >> 3, c = idx & 7;
        asrc[i] = Ag + (long)r * lda + c * 4;
        adst[i] = (uint32_t)(r * 128 + ((c ^ (r & 7)) << 4));
    }
    const float* bsrc[8]; uint32_t bdst[8];
    #pragma unroll
    for (int i = 0; i < 8; i++) {
        int idx = tid + i * 256;          // 2048 chunks: row 0..255
        int r = idx >> 3, c = idx & 7;
        bsrc[i] = Bg + (long)r * ldb + c * 4;
        bdst[i] = (uint32_t)(16384 + r * 128 + ((c ^ (r & 7)) << 4));
    }

    // ---- ldmatrix per-thread base offsets ----
    // A frag (m16k8): m0=rows lo/k lo, m1=rows hi/k lo, m2=rows lo/k hi, m3=hi/hi
    const int rx   = lane & 7;
    const int a_r  = (lane & 7) + (((lane >> 3) & 1) << 3);
    const int a_cs = (lane >> 4) & 1;
    // B frag pair: m0=rows lo/k lo (b0,nt even), m1=lo/hi (b1), m2=hi/lo, m3=hi/hi
    const int b_r  = (lane & 7) + (((lane >> 4) & 1) << 3);
    const int b_cs = (lane >> 3) & 1;
    uint32_t aoff[4], boff[4];
    #pragma unroll
    for (int i = 0; i < 4; i++) aoff[i] = (uint32_t)((wm * 64 + i * 16 + a_r) * 128);
    #pragma unroll
    for (int t = 0; t < 4; t++) boff[t] = (uint32_t)(16384 + (wn * 64 + t * 16 + b_r) * 128);

    float acc[4][8][4];
    #pragma unroll
    for (int i = 0; i < 4; i++)
        #pragma unroll
        for (int j = 0; j < 8; j++)
            #pragma unroll
            for (int e = 0; e < 4; e++) acc[i][j][e] = 0.0f;

    // ---- prologue: stages 0..2 ----
    #pragma unroll
    for (int s = 0; s < STAGES - 1; s++) {
        uint32_t base = sb + s * STAGE_BYTES;
        #pragma unroll
        for (int i = 0; i < 4; i++) cp16(base + adst[i], asrc[i] + (long)s * 32);
        #pragma unroll
        for (int i = 0; i < 8; i++) cp16(base + bdst[i], bsrc[i] + (long)s * 32);
        asm volatile("cp.async.commit_group;" ::: "memory");
    }

    for (int k = 0; k < nk; k++) {
        const int rem = nk - 1 - k;
        if (rem >= 2)      asm volatile("cp.async.wait_group 2;" ::: "memory");
        else if (rem == 1) asm volatile("cp.async.wait_group 1;" ::: "memory");
        else               asm volatile("cp.async.wait_group 0;" ::: "memory");
        __syncthreads();

        // issue stage k+3 (slot freed by compute of k-1, guaranteed by the sync)
        const int kp = k + STAGES - 1;
        if (kp < nk) {
            uint32_t base = sb + (kp & 3) * STAGE_BYTES;
            #pragma unroll
            for (int i = 0; i < 4; i++) cp16(base + adst[i], asrc[i] + (long)kp * 32);
            #pragma unroll
            for (int i = 0; i < 8; i++) cp16(base + bdst[i], bsrc[i] + (long)kp * 32);
            asm volatile("cp.async.commit_group;" ::: "memory");
        }

        // compute chunk k from slot k&3
        const uint32_t st = sb + (k & 3) * STAGE_BYTES;
        #pragma unroll
        for (int kk = 0; kk < 4; kk++) {
            uint32_t af[4][4], bf[4][4];
            #pragma unroll
            for (int i = 0; i < 4; i++)
                ldsm4(af[i], st + aoff[i] + (uint32_t)((((kk << 1) + a_cs) ^ rx) << 4));
            #pragma unroll
            for (int t = 0; t < 4; t++)
                ldsm4(bf[t], st + boff[t] + (uint32_t)((((kk << 1) + b_cs) ^ rx) << 4));
            #pragma unroll
            for (int i = 0; i < 4; i++)
                #pragma unroll
                for (int j = 0; j < 8; j++)
                    mma8(acc[i][j], af[i], bf[j >> 1][(j & 1) << 1],
                         bf[j >> 1][((j & 1) << 1) + 1]);
        }
    }

    // ---- epilogue: direct gmem stores (float2), fused bias/relu/round ----
    float* Cz = C + (long)z * c_z;
    const float* bz = bias + (long)z * bias_z;
    const int g  = lane >> 2;
    const int tg = lane & 3;
    #pragma unroll
    for (int i = 0; i < 4; i++) {
        const long row0 = m0 + wm * 64 + i * 16 + g;
        #pragma unroll
        for (int j = 0; j < 8; j++) {
            const long col = n0 + wn * 64 + j * 8 + tg * 2;
            float2 v0 = make_float2(acc[i][j][0], acc[i][j][1]);
            float2 v1 = make_float2(acc[i][j][2], acc[i][j][3]);
            if (flags & 1) {
                float2 b = *(const float2*)(bz + col);
                v0.x += b.x; v0.y += b.y; v1.x += b.x; v1.y += b.y;
            }
            if (flags & 2) {
                v0.x = to_tf32(fmaxf(v0.x, 0.f)); v0.y = to_tf32(fmaxf(v0.y, 0.f));
                v1.x = to_tf32(fmaxf(v1.x, 0.f)); v1.y = to_tf32(fmaxf(v1.y, 0.f));
            }
            *(float2*)(Cz + row0 * ldc + col)       = v0;
            *(float2*)(Cz + (row0 + 8) * ldc + col) = v1;
        }
    }
}

// ---------------- prep / post kernels --------------------------------------
__global__ void round_x_k(const float* __restrict__ x, float* __restrict__ xr) {
    long i = (long)blockIdx.x * 256 + threadIdx.x;     // float4 index
    float4 v = ((const float4*)x)[i];
    v.x = to_tf32(v.x); v.y = to_tf32(v.y); v.z = to_tf32(v.z); v.w = to_tf32(v.w);
    ((float4*)xr)[i] = v;
}

// in: [z][K][N] row-major -> out[z*out_z + n*out_ld + z*out_colz + k] = tf32(in)
__global__ void transpose_cvt(const float* __restrict__ in, float* __restrict__ out,
                              int K, int N, long in_z, long out_z,
                              long out_ld, long out_colz)
{
    __shared__ float t[32][33];
    int z = blockIdx.z;
    const float* I = in + (long)z * in_z;
    float* O = out + (long)z * out_z + (long)z * out_colz;
    int n0 = blockIdx.x * 32, k0 = blockIdx.y * 32;
    int tx = threadIdx.x, ty = threadIdx.y;
    #pragma unroll
    for (int i = 0; i < 32; i += 8)
        t[ty + i][tx] = I[(long)(k0 + ty + i) * N + n0 + tx];
    __syncthreads();
    #pragma unroll
    for (int i = 0; i < 32; i += 8)
        O[(long)(n0 + ty + i) * out_ld + k0 + tx] = to_tf32(t[tx][ty + i]);
}

__global__ void reduce_k(const float* __restrict__ part, const float* __restrict__ b3,
                         float* __restrict__ out)
{
    long i = (long)blockIdx.x * 256 + threadIdx.x;   // float4 idx
    float4 a = ((const float4*)part)[i];
    #pragma unroll
    for (int s = 1; s < SPLITK; s++) {
        float4 v = ((const float4*)part)[(long)s * ((long)B_ * DOUT / 4) + i];
        a.x += v.x; a.y += v.y; a.z += v.z; a.w += v.w;
    }
    int o4 = (int)(i & (DOUT / 4 - 1));
    float4 bs = make_float4(0.f, 0.f, 0.f, 0.f);
    #pragma unroll
    for (int t = 0; t < T_; t++) {
        float4 b = ((const float4*)b3)[t * (DOUT / 4) + o4];
        bs.x += b.x; bs.y += b.y; bs.z += b.z; bs.w += b.w;
    }
    const float s = 1.0f / T_;
    float4 o;
    o.x = (a.x + bs.x) * s; o.y = (a.y + bs.y) * s;
    o.z = (a.z + bs.z) * s; o.w = (a.w + bs.w) * s;
    ((float4*)out)[i] = o;
}

// ---------------- launcher --------------------------------------------------
extern "C" void kernel_launch(void* const* d_in, const int* in_sizes, int n_in,
                              void* d_out, int out_size)
{
    const float* x  = (const float*)d_in[0];
    const float* W1 = (const float*)d_in[1];
    const float* b1 = (const float*)d_in[2];
    const float* W2 = (const float*)d_in[3];
    const float* b2 = (const float*)d_in[4];
    const float* W3 = (const float*)d_in[5];
    const float* b3 = (const float*)d_in[6];
    float* out = (float*)d_out;

    float *xr, *w1t, *w2t, *w3t, *h1, *h2, *part;
    cudaGetSymbolAddress((void**)&xr,   g_x);
    cudaGetSymbolAddress((void**)&w1t,  g_w1t);
    cudaGetSymbolAddress((void**)&w2t,  g_w2t);
    cudaGetSymbolAddress((void**)&w3t,  g_w3t);
    cudaGetSymbolAddress((void**)&h1,   g_h1);
    cudaGetSymbolAddress((void**)&h2,   g_h2);
    cudaGetSymbolAddress((void**)&part, g_part);

    cudaFuncSetAttribute(gemm_tc, cudaFuncAttributeMaxDynamicSharedMemorySize, GEMM_SMEM);

    // prep: tf32-round x; transpose+round weights to [n][k] K-major
    round_x_k<<<(B_ * DIN / 4) / 256, 256>>>(x, xr);
    transpose_cvt<<<dim3(DH / 32, DIN / 32, T_), dim3(32, 8)>>>(
        W1, w1t, DIN, DH, (long)DIN * DH, (long)DH * DIN, DIN, 0);
    transpose_cvt<<<dim3(DH / 32, DH / 32, T_), dim3(32, 8)>>>(
        W2, w2t, DH, DH, (long)DH * DH, (long)DH * DH, DH, 0);
    transpose_cvt<<<dim3(DOUT / 32, DH / 32, T_), dim3(32, 8)>>>(
        W3, w3t, DH, DOUT, (long)DH * DOUT, 0, (long)T_ * DH, DH);

    // L1: h1[b][t*DH+n] = relu(x @ W1[t] + b1[t]),  K=512
    gemm_tc<<<dim3(B_ / 128, DH / 256, T_), 256, GEMM_SMEM>>>(
        xr, w1t, b1, h1,
        DIN / 32, DIN, DIN, (long)T_ * DH,
        0, (long)DH * DIN, DH, DH, /*flags=*/3);

    // L2: h2[b][t*DH+n] = relu(h1_t @ W2[t] + b2[t]),  K=1024
    gemm_tc<<<dim3(B_ / 128, DH / 256, T_), 256, GEMM_SMEM>>>(
        h1, w2t, b2, h2,
        DH / 32, (long)T_ * DH, DH, (long)T_ * DH,
        DH, (long)DH * DH, DH, DH, /*flags=*/3);

    // L3: split-K over K=16384 -> partials (no bias, no relu)
    gemm_tc<<<dim3(B_ / 128, 1, SPLITK), 256, GEMM_SMEM>>>(
        h2, w3t, b3, part,
        KSEG / 32, (long)T_ * DH, (long)T_ * DH, DOUT,
        KSEG, KSEG, (long)B_ * DOUT, 0, /*flags=*/0);

    // reduce partials + mean + summed bias
    reduce_k<<<(B_ * DOUT / 4) / 256, 256>>>(part, b3, out);
}

// round 5
// speedup vs baseline: 6.9157x; 1.8186x over previous
#include <cuda_runtime.h>
#include <cuda_fp16.h>
#include <cstdint>

#define T_   16
#define B_   8192
#define DIN  512
#define DH   1024
#define DOUT 256
#define SPLITK 8
#define KSEG (T_*DH/SPLITK)   // 2048

// ---------------- scratch (allocation-free: __device__ globals) -------------
__device__ __half g_xh [(size_t)B_*DIN];          // x fp16
__device__ __half g_w1t[(size_t)T_*DH*DIN];       // W1^T [t][n][k] fp16
__device__ __half g_w2t[(size_t)T_*DH*DH];        // W2^T [t][n][k] fp16
__device__ __half g_w3t[(size_t)DOUT*T_*DH];      // W3^T [n][t*DH+k] fp16
__device__ __half g_h1 [(size_t)B_*T_*DH];        // h1 [b][t][h] fp16
__device__ __half g_h2 [(size_t)B_*T_*DH];        // h2 [b][t][h] fp16
__device__ float  g_part[(size_t)SPLITK*B_*DOUT]; // split-K partials fp32

// ---------------- helpers ---------------------------------------------------
__device__ __forceinline__ uint32_t smem_to_u32(const void* p) {
    uint32_t a;
    asm("{ .reg .u64 t; cvta.to.shared.u64 t, %1; cvt.u32.u64 %0, t; }"
        : "=r"(a) : "l"(p));
    return a;
}
__device__ __forceinline__ void cp16(uint32_t s, const void* g) {
    asm volatile("cp.async.cg.shared.global [%0], [%1], 16;" :: "r"(s), "l"(g));
}
__device__ __forceinline__ void ldsm4(uint32_t* r, uint32_t addr) {
    asm volatile("ldmatrix.sync.aligned.m8n8.x4.shared.b16 {%0,%1,%2,%3}, [%4];"
        : "=r"(r[0]), "=r"(r[1]), "=r"(r[2]), "=r"(r[3]) : "r"(addr));
}
__device__ __forceinline__ void mma16(float* d, const uint32_t* a,
                                      uint32_t b0, uint32_t b1) {
    asm volatile(
        "mma.sync.aligned.m16n8k16.row.col.f32.f16.f16.f32 "
        "{%0,%1,%2,%3}, {%4,%5,%6,%7}, {%8,%9}, {%0,%1,%2,%3};"
        : "+f"(d[0]), "+f"(d[1]), "+f"(d[2]), "+f"(d[3])
        : "r"(a[0]), "r"(a[1]), "r"(a[2]), "r"(a[3]), "r"(b0), "r"(b1));
}

// ---------------- GEMM kernel ----------------------------------------------
// BM=128, BN=256, BK=64 halves (128B rows, same swizzle geometry as the tf32
// version). 256 threads = 8 warps as 2(M) x 4(N), warp tile 64x64,
// m16n8k16 fp16 mma, fp32 accumulate. 4-stage cp.async ring.
constexpr int STAGES      = 4;
constexpr int STAGE_BYTES = (128 + 256) * 128;             // 49152
constexpr int GEMM_SMEM   = STAGES * STAGE_BYTES;          // 196608

// flags: bit0 = add bias, bit1 = relu, bit2 = fp16 output (else fp32)
__global__ void __launch_bounds__(256, 1)
gemm_tc(const __half* __restrict__ A, const __half* __restrict__ B,
        const float* __restrict__ bias, void* __restrict__ Cv,
        int nk, long lda, long ldb, long ldc,
        long a_z, long b_z, long c_z, long bias_z, int flags)
{
    extern __shared__ char smem[];
    const uint32_t sb = smem_to_u32(smem);
    const int tid  = threadIdx.x;
    const int lane = tid & 31;
    const int wid  = tid >> 5;
    const int wm   = wid & 1;        // 2 M warp-rows (64 each)
    const int wn   = wid >> 1;       // 4 N warp-cols (64 each)
    const int z    = blockIdx.z;
    const long m0  = (long)blockIdx.x * 128;
    const long n0  = (long)blockIdx.y * 256;

    const __half* Ag = A + (long)z * a_z + m0 * lda;
    const __half* Bg = B + (long)z * b_z + n0 * ldb;

    // ---- cp.async source pointers / swizzled dest offsets ----
    // One 16B chunk = 8 halves. A: 128 rows x 8 chunks; B: 256 rows x 8 chunks.
    const __half* asrc[4]; uint32_t adst[4];
    #pragma unroll
    for (int i = 0; i < 4; i++) {
        int idx = tid + i * 256;
        int r = idx >> 3, c = idx & 7;
        asrc[i] = Ag + (long)r * lda + c * 8;
        adst[i] = (uint32_t)(r * 128 + ((c ^ (r & 7)) << 4));
    }
    const __half* bsrc[8]; uint32_t bdst[8];
    #pragma unroll
    for (int i = 0; i < 8; i++) {
        int idx = tid + i * 256;
        int r = idx >> 3, c = idx & 7;
        bsrc[i] = Bg + (long)r * ldb + c * 8;
        bdst[i] = (uint32_t)(16384 + r * 128 + ((c ^ (r & 7)) << 4));
    }

    // ---- ldmatrix per-thread base offsets (identical geometry to tf32 ver) --
    const int rx   = lane & 7;
    const int a_r  = (lane & 7) + (((lane >> 3) & 1) << 3);
    const int a_cs = (lane >> 4) & 1;           // k-half within k16
    const int b_r  = (lane & 7) + (((lane >> 4) & 1) << 3);
    const int b_cs = (lane >> 3) & 1;
    uint32_t aoff[4], boff[4];
    #pragma unroll
    for (int i = 0; i < 4; i++) aoff[i] = (uint32_t)((wm * 64 + i * 16 + a_r) * 128);
    #pragma unroll
    for (int t = 0; t < 4; t++) boff[t] = (uint32_t)(16384 + (wn * 64 + t * 16 + b_r) * 128);

    float acc[4][8][4];
    #pragma unroll
    for (int i = 0; i < 4; i++)
        #pragma unroll
        for (int j = 0; j < 8; j++)
            #pragma unroll
            for (int e = 0; e < 4; e++) acc[i][j][e] = 0.0f;

    // ---- prologue: stages 0..2 ----
    #pragma unroll
    for (int s = 0; s < STAGES - 1; s++) {
        uint32_t base = sb + s * STAGE_BYTES;
        #pragma unroll
        for (int i = 0; i < 4; i++) cp16(base + adst[i], asrc[i] + (long)s * 64);
        #pragma unroll
        for (int i = 0; i < 8; i++) cp16(base + bdst[i], bsrc[i] + (long)s * 64);
        asm volatile("cp.async.commit_group;" ::: "memory");
    }

    for (int k = 0; k < nk; k++) {
        const int rem = nk - 1 - k;
        if (rem >= 2)      asm volatile("cp.async.wait_group 2;" ::: "memory");
        else if (rem == 1) asm volatile("cp.async.wait_group 1;" ::: "memory");
        else               asm volatile("cp.async.wait_group 0;" ::: "memory");
        __syncthreads();

        const int kp = k + STAGES - 1;
        if (kp < nk) {
            uint32_t base = sb + (kp & 3) * STAGE_BYTES;
            #pragma unroll
            for (int i = 0; i < 4; i++) cp16(base + adst[i], asrc[i] + (long)kp * 64);
            #pragma unroll
            for (int i = 0; i < 8; i++) cp16(base + bdst[i], bsrc[i] + (long)kp * 64);
            asm volatile("cp.async.commit_group;" ::: "memory");
        }

        // compute chunk k (64 K-elems = 4 x k16) from slot k&3
        const uint32_t st = sb + (k & 3) * STAGE_BYTES;
        #pragma unroll
        for (int kk = 0; kk < 4; kk++) {
            uint32_t af[4][4], bf[4][4];
            #pragma unroll
            for (int i = 0; i < 4; i++)
                ldsm4(af[i], st + aoff[i] + (uint32_t)((((kk << 1) + a_cs) ^ rx) << 4));
            #pragma unroll
            for (int t = 0; t < 4; t++)
                ldsm4(bf[t], st + boff[t] + (uint32_t)((((kk << 1) + b_cs) ^ rx) << 4));
            #pragma unroll
            for (int i = 0; i < 4; i++)
                #pragma unroll
                for (int j = 0; j < 8; j++)
                    mma16(acc[i][j], af[i], bf[j >> 1][(j & 1) << 1],
                          bf[j >> 1][((j & 1) << 1) + 1]);
        }
    }

    // ---- epilogue: fused bias / relu, fp16 or fp32 stores ----
    const float* bz = bias + (long)z * bias_z;
    const int g  = lane >> 2;
    const int tg = lane & 3;
    #pragma unroll
    for (int i = 0; i < 4; i++) {
        const long row0 = m0 + wm * 64 + i * 16 + g;
        #pragma unroll
        for (int j = 0; j < 8; j++) {
            const long col = n0 + wn * 64 + j * 8 + tg * 2;
            float2 v0 = make_float2(acc[i][j][0], acc[i][j][1]);
            float2 v1 = make_float2(acc[i][j][2], acc[i][j][3]);
            if (flags & 1) {
                float2 b = *(const float2*)(bz + col);
                v0.x += b.x; v0.y += b.y; v1.x += b.x; v1.y += b.y;
            }
            if (flags & 2) {
                v0.x = fmaxf(v0.x, 0.f); v0.y = fmaxf(v0.y, 0.f);
                v1.x = fmaxf(v1.x, 0.f); v1.y = fmaxf(v1.y, 0.f);
            }
            if (flags & 4) {
                __half* Cz = (__half*)Cv + (long)z * c_z;
                *(__half2*)(Cz + row0 * ldc + col) =
                    __floats2half2_rn(v0.x, v0.y);
                *(__half2*)(Cz + (row0 + 8) * ldc + col) =
                    __floats2half2_rn(v1.x, v1.y);
            } else {
                float* Cz = (float*)Cv + (long)z * c_z;
                *(float2*)(Cz + row0 * ldc + col)       = v0;
                *(float2*)(Cz + (row0 + 8) * ldc + col) = v1;
            }
        }
    }
}

// ---------------- prep / post kernels --------------------------------------
__global__ void cvt_x_h(const float* __restrict__ x, __half* __restrict__ xh) {
    long i = (long)blockIdx.x * 256 + threadIdx.x;     // float4 index
    float4 v = ((const float4*)x)[i];
    ((__half2*)xh)[i * 2 + 0] = __floats2half2_rn(v.x, v.y);
    ((__half2*)xh)[i * 2 + 1] = __floats2half2_rn(v.z, v.w);
}

// in: [z][K][N] fp32 row-major -> out[z*out_z + n*out_ld + z*out_colz + k] fp16
__global__ void transpose_cvt(const float* __restrict__ in, __half* __restrict__ out,
                              int K, int N, long in_z, long out_z,
                              long out_ld, long out_colz)
{
    __shared__ float t[32][33];
    int z = blockIdx.z;
    const float* I = in + (long)z * in_z;
    __half* O = out + (long)z * out_z + (long)z * out_colz;
    int n0 = blockIdx.x * 32, k0 = blockIdx.y * 32;
    int tx = threadIdx.x, ty = threadIdx.y;
    #pragma unroll
    for (int i = 0; i < 32; i += 8)
        t[ty + i][tx] = I[(long)(k0 + ty + i) * N + n0 + tx];
    __syncthreads();
    #pragma unroll
    for (int i = 0; i < 32; i += 8)
        O[(long)(n0 + ty + i) * out_ld + k0 + tx] = __float2half_rn(t[tx][ty + i]);
}

__global__ void reduce_k(const float* __restrict__ part, const float* __restrict__ b3,
                         float* __restrict__ out)
{
    long i = (long)blockIdx.x * 256 + threadIdx.x;   // float4 idx
    float4 a = ((const float4*)part)[i];
    #pragma unroll
    for (int s = 1; s < SPLITK; s++) {
        float4 v = ((const float4*)part)[(long)s * ((long)B_ * DOUT / 4) + i];
        a.x += v.x; a.y += v.y; a.z += v.z; a.w += v.w;
    }
    int o4 = (int)(i & (DOUT / 4 - 1));
    float4 bs = make_float4(0.f, 0.f, 0.f, 0.f);
    #pragma unroll
    for (int t = 0; t < T_; t++) {
        float4 b = ((const float4*)b3)[t * (DOUT / 4) + o4];
        bs.x += b.x; bs.y += b.y; bs.z += b.z; bs.w += b.w;
    }
    const float s = 1.0f / T_;
    float4 o;
    o.x = (a.x + bs.x) * s; o.y = (a.y + bs.y) * s;
    o.z = (a.z + bs.z) * s; o.w = (a.w + bs.w) * s;
    ((float4*)out)[i] = o;
}

// ---------------- launcher --------------------------------------------------
extern "C" void kernel_launch(void* const* d_in, const int* in_sizes, int n_in,
                              void* d_out, int out_size)
{
    const float* x  = (const float*)d_in[0];
    const float* W1 = (const float*)d_in[1];
    const float* b1 = (const float*)d_in[2];
    const float* W2 = (const float*)d_in[3];
    const float* b2 = (const float*)d_in[4];
    const float* W3 = (const float*)d_in[5];
    const float* b3 = (const float*)d_in[6];
    float* out = (float*)d_out;

    __half *xh, *w1t, *w2t, *w3t, *h1, *h2;
    float* part;
    cudaGetSymbolAddress((void**)&xh,   g_xh);
    cudaGetSymbolAddress((void**)&w1t,  g_w1t);
    cudaGetSymbolAddress((void**)&w2t,  g_w2t);
    cudaGetSymbolAddress((void**)&w3t,  g_w3t);
    cudaGetSymbolAddress((void**)&h1,   g_h1);
    cudaGetSymbolAddress((void**)&h2,   g_h2);
    cudaGetSymbolAddress((void**)&part, g_part);

    cudaFuncSetAttribute(gemm_tc, cudaFuncAttributeMaxDynamicSharedMemorySize, GEMM_SMEM);

    // prep: x -> fp16; weights -> fp16 transposed [n][k]
    cvt_x_h<<<(B_ * DIN / 4) / 256, 256>>>(x, xh);
    transpose_cvt<<<dim3(DH / 32, DIN / 32, T_), dim3(32, 8)>>>(
        W1, w1t, DIN, DH, (long)DIN * DH, (long)DH * DIN, DIN, 0);
    transpose_cvt<<<dim3(DH / 32, DH / 32, T_), dim3(32, 8)>>>(
        W2, w2t, DH, DH, (long)DH * DH, (long)DH * DH, DH, 0);
    transpose_cvt<<<dim3(DOUT / 32, DH / 32, T_), dim3(32, 8)>>>(
        W3, w3t, DH, DOUT, (long)DH * DOUT, 0, (long)T_ * DH, DH);

    // L1: h1[b][t*DH+n] = relu(x @ W1[t] + b1[t]),  K=512 -> nk=8
    gemm_tc<<<dim3(B_ / 128, DH / 256, T_), 256, GEMM_SMEM>>>(
        xh, w1t, b1, h1,
        DIN / 64, DIN, DIN, (long)T_ * DH,
        0, (long)DH * DIN, DH, DH, /*flags=*/7);

    // L2: h2[b][t*DH+n] = relu(h1_t @ W2[t] + b2[t]),  K=1024 -> nk=16
    gemm_tc<<<dim3(B_ / 128, DH / 256, T_), 256, GEMM_SMEM>>>(
        h1, w2t, b2, h2,
        DH / 64, (long)T_ * DH, DH, (long)T_ * DH,
        DH, (long)DH * DH, DH, DH, /*flags=*/7);

    // L3: split-K over K=16384 -> fp32 partials (no bias/relu), nk=32
    gemm_tc<<<dim3(B_ / 128, 1, SPLITK), 256, GEMM_SMEM>>>(
        h2, w3t, b3, part,
        KSEG / 64, (long)T_ * DH, (long)T_ * DH, DOUT,
        KSEG, KSEG, (long)B_ * DOUT, 0, /*flags=*/0);

    // reduce partials + mean + summed bias
    reduce_k<<<(B_ * DOUT / 4) / 256, 256>>>(part, b3, out);
}